// round 7
// baseline (speedup 1.0000x reference)
#include <cuda_runtime.h>

// QHadamard: y = FWHT_4096(x) / 64, rows = 8192, DIM = 4096.
// R4's 3-pass / 2-transpose structure (A: bits{5..9}, B: bits{0..4}, C: bits{10,11})
// with a cp.async 2-deep pipeline: each block handles 8 consecutive rows,
// prefetching row i+2 into the smem ring while computing row i.
// Unified smem swizzle (float4 units): q_phys = q ^ ((q>>3)&7)
// == R4's  phys(e) = e ^ ((e & 0xE0) >> 3); all phases conflict-free.

#define DIM 4096
#define THREADS 128
#define RPB 8                      // rows per block

__device__ __forceinline__ void bfly(float& a, float& b) {
    float t = a; a = t + b; b = t - b;
}

__device__ __forceinline__ void fwht32(float* x) {
#pragma unroll
    for (int h = 1; h < 32; h <<= 1)
#pragma unroll
        for (int i = 0; i < 32; i += (h << 1))
#pragma unroll
            for (int j = i; j < i + h; ++j) bfly(x[j], x[j + h]);
}

// Prefetch one full row (4096 floats) into smem buffer with the unified swizzle.
__device__ __forceinline__ void prefetch_row(const float* gsrc, unsigned sdst_base, int T) {
    const float4* s4 = reinterpret_cast<const float4*>(gsrc);
#pragma unroll
    for (int r = 0; r < 8; ++r) {
        const int q = r * THREADS + T;                       // logical float4 index
        const unsigned dst = sdst_base + 16u * (unsigned)(q ^ ((q >> 3) & 7));
        asm volatile("cp.async.cg.shared.global [%0], [%1], 16;\n"
                     :: "r"(dst), "l"(s4 + q));
    }
    asm volatile("cp.async.commit_group;\n" ::: "memory");
}

__global__ void __launch_bounds__(THREADS, 7)
QHadamard_24524263260380_kernel(const float* __restrict__ in,
                                float* __restrict__ out) {
    __shared__ float P[2][DIM];                              // 32 KB ring

    const int    T    = threadIdx.x;                         // 0..127
    const size_t row0 = (size_t)blockIdx.x * RPB;

    const unsigned pb0 = (unsigned)__cvta_generic_to_shared(P[0]);
    const unsigned pb1 = (unsigned)__cvta_generic_to_shared(P[1]);

    // Warm the pipeline: rows row0, row0+1.
    prefetch_row(in + row0 * DIM, pb0, T);
    prefetch_row(in + (row0 + 1) * DIM, pb1, T);

    const float scale  = 0.015625f;                          // 1/sqrt(4096)
    const int   abase  = (T & 31) + ((T >> 5) << 10);        // e{0..4}, e{10,11}
    const int   Tq     = T & 7;
    const int   base4  = T * 8;
    const int   cbase4 = (T & 31) + (((T >> 5) & 3) << 5);
    const int   cxor4  = (T >> 3) & 7;

    for (int i = 0; i < RPB; ++i) {
        if (i + 1 < RPB) { asm volatile("cp.async.wait_group 1;\n" ::: "memory"); }
        else             { asm volatile("cp.async.wait_group 0;\n" ::: "memory"); }
        __syncthreads();                                     // buffer visible to all

        float* Pb = P[i & 1];

        // ---- Pass A: in-place FWHT over bits {5..9} (each thread owns its
        //      elements exclusively -> read & write back without a barrier) ----
        float x[32];
#pragma unroll
        for (int k = 0; k < 32; ++k)
            x[k] = Pb[(abase + (k << 5)) ^ ((k & 7) << 2)];
#pragma unroll
        for (int k = 0; k < 32; ++k) x[k] *= scale;
        fwht32(x);
#pragma unroll
        for (int k = 0; k < 32; ++k)
            Pb[(abase + (k << 5)) ^ ((k & 7) << 2)] = x[k];
        __syncthreads();

        // ---- Pass B: 32 contiguous elements/thread, float4 in-place,
        //      FWHT over bits {0..4} ----
        float4* s4 = reinterpret_cast<float4*>(Pb);
        float y[32];
#pragma unroll
        for (int r = 0; r < 8; ++r) {
            float4 v = s4[base4 + (r ^ Tq)];
            y[r*4+0] = v.x; y[r*4+1] = v.y; y[r*4+2] = v.z; y[r*4+3] = v.w;
        }
        fwht32(y);
#pragma unroll
        for (int r = 0; r < 8; ++r)
            s4[base4 + (r ^ Tq)] = make_float4(y[r*4+0], y[r*4+1], y[r*4+2], y[r*4+3]);
        __syncthreads();

        // ---- Pass C: read float4, radix-4 over bits {10,11}, dense STG.128 ----
        float z[32];
#pragma unroll
        for (int rr = 0; rr < 4; ++rr)
#pragma unroll
            for (int s9 = 0; s9 < 2; ++s9) {
                float4 v = s4[(cbase4 + (s9 << 7) + (rr << 8)) ^ cxor4];
                const int ix = (rr << 3) + (s9 << 2);
                z[ix] = v.x; z[ix+1] = v.y; z[ix+2] = v.z; z[ix+3] = v.w;
            }
        __syncthreads();                    // all reads of Pb done -> refill is safe

        // Start the next prefetch into this (now free) buffer ASAP.
        if (i + 2 < RPB)
            prefetch_row(in + (row0 + i + 2) * DIM, (i & 1) ? pb1 : pb0, T);

        // FWHT over bits {10,11} = z-index bits {3,4}
#pragma unroll
        for (int hi = 0; hi < 32; hi += 16)
#pragma unroll
            for (int j = 0; j < 8; ++j) bfly(z[hi + j], z[hi + j + 8]);
#pragma unroll
        for (int j = 0; j < 16; ++j) bfly(z[j], z[j + 16]);

        float4* o4 = reinterpret_cast<float4*>(out + (row0 + i) * DIM);
#pragma unroll
        for (int rr = 0; rr < 4; ++rr)
#pragma unroll
            for (int s9 = 0; s9 < 2; ++s9) {
                const int ix = (rr << 3) + (s9 << 2);
                o4[cbase4 + (s9 << 7) + (rr << 8)] =
                    make_float4(z[ix], z[ix+1], z[ix+2], z[ix+3]);
            }
    }
}

extern "C" void kernel_launch(void* const* d_in, const int* in_sizes, int n_in,
                              void* d_out, int out_size) {
    const float* x   = (const float*)d_in[0];
    float*       out = (float*)d_out;
    const int rows = in_sizes[0] / DIM;              // 8192
    QHadamard_24524263260380_kernel<<<rows / RPB, THREADS>>>(x, out);
}

// round 8
// speedup vs baseline: 1.0987x; 1.0987x over previous
#include <cuda_runtime.h>

// QHadamard: y = FWHT_4096(x) / 64, rows = 8192, DIM = 4096.
// R4 structure (proven fastest): 3 register passes, 2 smem transposes, 0 shuffles.
//   A: bits {5..9}  (thread owns e{0..4} lanes + e{10,11} warp; scalar LDG/STS)
//   B: bits {0..4}  (32 contiguous elem/thread; float4 smem in-place)
//   C: bits {10,11} (float4 smem read; dense float4 STG)
// Swizzle phys(e) = e ^ ((e & 0xE0) >> 3) -- conflict-free in all phases.
// R8 change: packed f32x2 butterflies (PTX add/fma.rn.f32x2, sm_100+) for the
// upper 4 stages of passes A and B; lowest bit of each pass stays scalar.
// Cuts ~20% of issued instructions at identical memory traffic.

#define DIM 4096
#define THREADS 128

typedef unsigned long long u64;

#define NEG1_F32X2  0xBF800000BF800000ULL   // {-1.0f, -1.0f}
#define SC_F32X2    0x3C8000003C800000ULL   // {1/64, 1/64}

__device__ __forceinline__ void bfly(float& a, float& b) {
    float t = a; a = t + b; b = t - b;
}

__device__ __forceinline__ u64 pack2(float lo, float hi) {
    u64 r;
    asm("mov.b64 %0, {%1, %2};" : "=l"(r) : "f"(lo), "f"(hi));
    return r;
}
__device__ __forceinline__ void unpack2(u64 v, float& lo, float& hi) {
    asm("mov.b64 {%0, %1}, %2;" : "=f"(lo), "=f"(hi) : "l"(v));
}
// Packed butterfly: (a, b) -> (a + b, a - b) on two lanes at once.
__device__ __forceinline__ void pbfly(u64& a, u64& b, u64 neg1) {
    u64 s, d;
    asm("add.rn.f32x2 %0, %1, %2;" : "=l"(s) : "l"(a), "l"(b));
    asm("fma.rn.f32x2 %0, %1, %2, %3;" : "=l"(d) : "l"(b), "l"(neg1), "l"(a));
    a = s; b = d;
}
// FWHT-16 on 16 packed pairs (covers 4 element bits above the packing bit).
__device__ __forceinline__ void pfwht16(u64* v, u64 neg1) {
#pragma unroll
    for (int h = 1; h < 16; h <<= 1)
#pragma unroll
        for (int i = 0; i < 16; i += (h << 1))
#pragma unroll
            for (int j = i; j < i + h; ++j) pbfly(v[j], v[j + h], neg1);
}

// Full 32-point FWHT on x[0..31]: scalar stage on bit0, packed stages on bits 1..4.
// If do_scale, multiplies by 1/64 (packed) for free ordering.
template <bool DO_SCALE>
__device__ __forceinline__ void fwht32_packed(float* x) {
    const u64 neg1 = NEG1_F32X2;
#pragma unroll
    for (int j = 0; j < 16; ++j) bfly(x[2*j], x[2*j + 1]);   // bit 0, scalar
    u64 v[16];
#pragma unroll
    for (int j = 0; j < 16; ++j) v[j] = pack2(x[2*j], x[2*j + 1]);
    if (DO_SCALE) {
        const u64 sc = SC_F32X2;
#pragma unroll
        for (int j = 0; j < 16; ++j)
            asm("mul.rn.f32x2 %0, %1, %2;" : "=l"(v[j]) : "l"(v[j]), "l"(sc));
    }
    pfwht16(v, neg1);                                        // bits 1..4, packed
#pragma unroll
    for (int j = 0; j < 16; ++j) unpack2(v[j], x[2*j], x[2*j + 1]);
}

__global__ void __launch_bounds__(THREADS, 8)
QHadamard_24524263260380_kernel(const float* __restrict__ in,
                                float* __restrict__ out) {
    __shared__ float s[DIM];                      // 16 KB, swizzled layout

    const int    T   = threadIdx.x;               // 0..127
    const size_t row = (size_t)blockIdx.x * DIM;
    const float* g   = in + row;

    // ---- Pass A: e = (T&31) + k*32 + (T>>5)*1024, k = 0..31 -> bits {5..9} ----
    const int abase = (T & 31) + ((T >> 5) << 10);
    float x[32];
#pragma unroll
    for (int k = 0; k < 32; ++k) x[k] = g[abase + (k << 5)];

    fwht32_packed<true>(x);                       // FWHT bits 5..9, scale folded

    // ---- T1 write: s[swz(e)], swz = e ^ ((k&7)<<2). Banks = lane ^ const. ----
#pragma unroll
    for (int k = 0; k < 32; ++k) {
        s[(abase + (k << 5)) ^ ((k & 7) << 2)] = x[k];
    }
    __syncthreads();

    // ---- Pass B: thread T = e>>5 owns 32 contiguous elements. f4 in/out. ----
    float y[32];
    {
        const int base4 = T * 8;                  // float4 index of e = T*32
        float4* s4 = reinterpret_cast<float4*>(s);
#pragma unroll
        for (int r = 0; r < 8; ++r) {
            float4 v = s4[base4 + (r ^ (T & 7))];
            y[r*4+0] = v.x; y[r*4+1] = v.y; y[r*4+2] = v.z; y[r*4+3] = v.w;
        }
        fwht32_packed<false>(y);                  // FWHT bits 0..4
#pragma unroll
        for (int r = 0; r < 8; ++r) {
            s4[base4 + (r ^ (T & 7))] =
                make_float4(y[r*4+0], y[r*4+1], y[r*4+2], y[r*4+3]);
        }
    }
    __syncthreads();

    // ---- Pass C: base bits{2..6}=T&31, {7,8}=(T>>5)&3; owns {0,1,9,10,11} ----
    const int cbase4 = (T & 31) + (((T >> 5) & 3) << 5);   // float4 index
    const int cxor4  = (T >> 3) & 7;                       // swizzle in f4 units
    float z[32];
    {
        const float4* s4 = reinterpret_cast<const float4*>(s);
#pragma unroll
        for (int rr = 0; rr < 4; ++rr)
#pragma unroll
            for (int s9 = 0; s9 < 2; ++s9) {
                float4 v = s4[(cbase4 + (s9 << 7) + (rr << 8)) ^ cxor4];
                const int i = (rr << 3) + (s9 << 2);
                z[i] = v.x; z[i+1] = v.y; z[i+2] = v.z; z[i+3] = v.w;
            }
    }
    // FWHT over bits {10,11} = z-index bits {3,4}: packed on pairs (bit 0).
    {
        const u64 neg1 = NEG1_F32X2;
        u64 v[16];
#pragma unroll
        for (int j = 0; j < 16; ++j) v[j] = pack2(z[2*j], z[2*j + 1]);
#pragma unroll
        for (int hi = 0; hi < 16; hi += 8)        // z bit 3 -> v bit 2
#pragma unroll
            for (int j = 0; j < 4; ++j) pbfly(v[hi + j], v[hi + j + 4], neg1);
#pragma unroll
        for (int j = 0; j < 8; ++j) pbfly(v[j], v[j + 8], neg1);  // z bit 4
#pragma unroll
        for (int j = 0; j < 16; ++j) unpack2(v[j], z[2*j], z[2*j + 1]);
    }

    // ---- Dense float4 stores: per instr lanes write 32 contiguous float4 ----
    float4* o4 = reinterpret_cast<float4*>(out + row);
#pragma unroll
    for (int rr = 0; rr < 4; ++rr)
#pragma unroll
        for (int s9 = 0; s9 < 2; ++s9) {
            const int i = (rr << 3) + (s9 << 2);
            o4[cbase4 + (s9 << 7) + (rr << 8)] =
                make_float4(z[i], z[i+1], z[i+2], z[i+3]);
        }
}

extern "C" void kernel_launch(void* const* d_in, const int* in_sizes, int n_in,
                              void* d_out, int out_size) {
    const float* x   = (const float*)d_in[0];
    float*       out = (float*)d_out;
    const int rows = in_sizes[0] / DIM;            // 8192
    QHadamard_24524263260380_kernel<<<rows, THREADS>>>(x, out);
}